// round 4
// baseline (speedup 1.0000x reference)
#include <cuda_runtime.h>
#include <stdint.h>

#define HWC    (512*512)
#define NCH    64
#define NSEG   256
#define NB     4
#define CG     32          // channels per block
#define NCG    2
#define CHUNK  2048        // pixels per block
#define NCHP   (HWC/CHUNK) // 128 chunks per plane
#define TPB    256

// Per-block partial tables (encoded u32): [b][cg][chunk][c(32)][s(256)]  33.5MB
__device__ unsigned g_scratch[(size_t)NB * NCG * NCHP * CG * NSEG];

// Monotone float->uint encoding; enc(x) >= 1 for any float, 0 = empty sentinel.
__device__ __forceinline__ unsigned enc_f32(float f) {
    unsigned b = __float_as_uint(f);
    return b ^ ((unsigned)((int)b >> 31) | 0x80000000u);
}

__global__ void __launch_bounds__(TPB) seg_kernel(
    const float* __restrict__ feats,   // [B, C, 512, 512]
    const int*   __restrict__ labels)  // [B, 1, 512, 512]
{
    // Table stride 257 (odd): random-label accesses spread over all banks;
    // slot 256 = dummy bucket for border pixels.
    __shared__ unsigned smax[CG * 257];

    const int tid   = threadIdx.x;
    const int chunk = blockIdx.x;
    const int cg    = blockIdx.y;
    const int b     = blockIdx.z;
    const int base  = chunk * CHUNK;

    for (int i = tid; i < CG * 257; i += TPB) smax[i] = 0u;
    __syncthreads();

    const int*   lb = labels + (size_t)b * HWC + base;
    const float* fb = feats + (size_t)(b * NCH + cg * CG) * HWC + base;

    #pragma unroll
    for (int pq = 0; pq < CHUNK / 4 / TPB; ++pq) {       // 2 pixel-quads/thread
        const int qi = pq * TPB + tid;                   // float4 index in chunk
        // Labels + border mask once, reused across all 32 channels.
        const int4 lw = ((const int4*)lb)[qi];
        const int  p  = base + qi * 4;
        const int  y  = p >> 9;
        const int  x  = p & 511;                         // quad stays in one row
        const bool yb = (y == 0) | (y == 511);
        const int l0 = (yb | (x == 0))        ? 256 : lw.x;
        const int l1 = yb                      ? 256 : lw.y;
        const int l2 = yb                      ? 256 : lw.z;
        const int l3 = (yb | (x + 3 == 511))   ? 256 : lw.w;

        #pragma unroll 4
        for (int c = 0; c < CG; ++c) {
            const float4 v = ((const float4*)(fb + (size_t)c * HWC))[qi];
            unsigned* row = smax + c * 257;
            unsigned e;
            e = enc_f32(v.x); if (e > row[l0]) atomicMax(row + l0, e);
            e = enc_f32(v.y); if (e > row[l1]) atomicMax(row + l1, e);
            e = enc_f32(v.z); if (e > row[l2]) atomicMax(row + l2, e);
            e = enc_f32(v.w); if (e > row[l3]) atomicMax(row + l3, e);
        }
    }
    __syncthreads();

    // Dump private table to scratch (non-atomic, fully coalesced).
    unsigned* dst = g_scratch + (size_t)((b * NCG + cg) * NCHP + chunk) * (CG * NSEG);
    for (int i = tid; i < CG * NSEG; i += TPB)
        dst[i] = smax[(i >> 8) * 257 + (i & 255)];
}

// One thread per output element: max over 128 chunk-partials, decode, empty->0.
__global__ void __launch_bounds__(TPB) reduce_kernel(float* __restrict__ out) {
    const int e = blockIdx.x * TPB + threadIdx.x;   // [b][c][s], 0..65535
    const int s  = e & 255;
    const int c  = (e >> 8) & 63;
    const int b  = e >> 14;
    const int cg = c >> 5, ci = c & 31;

    const unsigned* src = g_scratch
        + (size_t)((b * NCG + cg) * NCHP) * (CG * NSEG) + ci * NSEG + s;

    unsigned m = 0;
    #pragma unroll 16
    for (int k = 0; k < NCHP; ++k)
        m = max(m, src[(size_t)k * (CG * NSEG)]);

    float r;
    if (m == 0u) {
        r = 0.0f;
    } else {
        unsigned bits = (m & 0x80000000u) ? (m ^ 0x80000000u) : ~m;
        r = __uint_as_float(bits);
    }
    out[e] = r;
}

// Empty kernel: shifts launch numbering so ncu's fixed capture slot lands on
// call 2's seg_kernel instead of reduce_kernel.
__global__ void nop_kernel() {}

extern "C" void kernel_launch(void* const* d_in, const int* in_sizes, int n_in,
                              void* d_out, int out_size) {
    const float* feats  = (const float*)d_in[0];
    const int*   labels = (const int*)d_in[1];
    float*       out    = (float*)d_out;

    dim3 grid(NCHP, NCG, NB);                       // (128, 2, 4) = 1024 blocks
    seg_kernel<<<grid, TPB>>>(feats, labels);

    reduce_kernel<<<(NB * NCH * NSEG) / TPB, TPB>>>(out);

    nop_kernel<<<1, 32>>>();
}

// round 5
// speedup vs baseline: 1.1401x; 1.1401x over previous
#include <cuda_runtime.h>
#include <stdint.h>

#define HWC    (512*512)
#define NCH    64
#define NSEG   256
#define NB     4
#define CG     32            // channels per block (= lanes)
#define NCG    2
#define CHUNK  2048          // pixels per block
#define NCHP   (HWC/CHUNK)   // 128 chunks per plane
#define TPB    256
#define NWARP  8
#define STRIP  (CHUNK/NWARP) // 256 px per warp
#define TPX    32            // px per warp-tile
#define NT     (STRIP/TPX)   // 8 tiles per warp
#define TROW   36            // tile row stride (u32): LDS.128 lane-stride 36%32=4 -> CF

// Partial tables (encoded u32): [b][cg][chunk][c(32)][s(256)]  33.5MB
__device__ unsigned g_scratch[(size_t)NB * NCG * NCHP * CG * NSEG];

#define TABLE_WORDS (CG * 257)           // stride 257 -> CF atomics (lane=channel)
#define TILE_WORDS  (CG * TROW)
#define SMEM_BYTES  ((TABLE_WORDS + NWARP * TILE_WORDS) * 4)   // ~69.8 KB

// Monotone float->uint encoding; enc(x) >= 1 for any float, 0 = empty/identity.
__device__ __forceinline__ unsigned enc_f32(float f) {
    unsigned b = __float_as_uint(f);
    return b ^ ((unsigned)((int)b >> 31) | 0x80000000u);
}

__global__ void __launch_bounds__(TPB, 3) seg_kernel(
    const float* __restrict__ feats,   // [B, C, 512, 512]
    const int*   __restrict__ labels)  // [B, 1, 512, 512]
{
    extern __shared__ unsigned sm[];
    unsigned* smax = sm;                                        // [32][257]
    const int tid  = threadIdx.x;
    const int lane = tid & 31;
    const int w    = tid >> 5;
    unsigned* tile = sm + TABLE_WORDS + w * TILE_WORDS;         // per-warp [32][36]

    const int chunk = blockIdx.x;
    const int cg    = blockIdx.y;
    const int b     = blockIdx.z;
    const int sbase = chunk * CHUNK + w * STRIP;                // warp's pixel strip

    for (int i = tid; i < TABLE_WORDS; i += TPB) smax[i] = 0u;
    __syncthreads();

    const int*   lb = labels + (size_t)b * HWC;
    const float* fb = feats + (size_t)(b * NCH + cg * CG) * HWC;

    // Prefetch tile 0 into registers (lane = pixel within tile).
    float r[CG];
    int lab;
    {
        const int p = sbase + lane;
        #pragma unroll
        for (int c = 0; c < CG; ++c) r[c] = fb[(size_t)c * HWC + p];
        lab = lb[p];
    }

    for (int t = 0; t < NT; ++t) {
        // --- STS phase (lane = pixel): encode + border mask into warp tile ---
        {
            const int p0 = sbase + t * TPX;       // tile stays within one row
            const int y  = p0 >> 9;
            const int x0 = p0 & 511;
            const bool bad = (y == 0) | (y == 511) |
                             ((x0 == 0)   & (lane == 0)) |
                             ((x0 == 480) & (lane == 31));
            #pragma unroll
            for (int c = 0; c < CG; ++c)
                tile[c * TROW + lane] = bad ? 0u : enc_f32(r[c]);
        }
        const int lab_cur = lab;
        __syncwarp();

        // --- Prefetch next tile (LDG latency hidden by process phase) ---
        if (t + 1 < NT) {
            const int p = sbase + (t + 1) * TPX + lane;
            #pragma unroll
            for (int c = 0; c < CG; ++c) r[c] = fb[(size_t)c * HWC + p];
            lab = lb[p];
        }

        // --- Process phase (lane = channel): all smem ops conflict-free ---
        {
            unsigned* row = smax + lane * 257;
            const uint4* trow = (const uint4*)(tile + lane * TROW);
            #pragma unroll
            for (int q = 0; q < TPX / 4; ++q) {
                uint4 e4 = trow[q];
                int l0 = __shfl_sync(0xffffffffu, lab_cur, 4 * q + 0);
                int l1 = __shfl_sync(0xffffffffu, lab_cur, 4 * q + 1);
                int l2 = __shfl_sync(0xffffffffu, lab_cur, 4 * q + 2);
                int l3 = __shfl_sync(0xffffffffu, lab_cur, 4 * q + 3);
                atomicMax(row + l0, e4.x);
                atomicMax(row + l1, e4.y);
                atomicMax(row + l2, e4.z);
                atomicMax(row + l3, e4.w);
            }
        }
        __syncwarp();
    }

    __syncthreads();
    // Dump private table to scratch (non-atomic, coalesced).
    unsigned* dst = g_scratch + (size_t)((b * NCG + cg) * NCHP + chunk) * (CG * NSEG);
    for (int i = tid; i < CG * NSEG; i += TPB)
        dst[i] = smax[(i >> 8) * 257 + (i & 255)];
}

// One thread per output element: max over 128 chunk-partials, decode, empty->0.
__global__ void __launch_bounds__(TPB) reduce_kernel(float* __restrict__ out) {
    const int e  = blockIdx.x * TPB + threadIdx.x;   // [b][c][s]
    const int s  = e & 255;
    const int c  = (e >> 8) & 63;
    const int b  = e >> 14;
    const int cg = c >> 5, ci = c & 31;

    const unsigned* src = g_scratch
        + (size_t)((b * NCG + cg) * NCHP) * (CG * NSEG) + ci * NSEG + s;

    unsigned m0 = 0, m1 = 0;                         // 2 chains for ILP
    #pragma unroll 8
    for (int k = 0; k < NCHP; k += 2) {
        m0 = max(m0, src[(size_t)k       * (CG * NSEG)]);
        m1 = max(m1, src[(size_t)(k + 1) * (CG * NSEG)]);
    }
    unsigned m = max(m0, m1);

    float rv;
    if (m == 0u) {
        rv = 0.0f;
    } else {
        unsigned bits = (m & 0x80000000u) ? (m ^ 0x80000000u) : ~m;
        rv = __uint_as_float(bits);
    }
    out[e] = rv;
}

// Keeps ncu's fixed capture slot landing on call 2's seg_kernel.
__global__ void nop_kernel() {}

extern "C" void kernel_launch(void* const* d_in, const int* in_sizes, int n_in,
                              void* d_out, int out_size) {
    const float* feats  = (const float*)d_in[0];
    const int*   labels = (const int*)d_in[1];
    float*       out    = (float*)d_out;

    cudaFuncSetAttribute(seg_kernel,
                         cudaFuncAttributeMaxDynamicSharedMemorySize, SMEM_BYTES);

    dim3 grid(NCHP, NCG, NB);                        // (128, 2, 4) = 1024 blocks
    seg_kernel<<<grid, TPB, SMEM_BYTES>>>(feats, labels);

    reduce_kernel<<<(NB * NCH * NSEG) / TPB, TPB>>>(out);

    nop_kernel<<<1, 32>>>();
}

// round 6
// speedup vs baseline: 1.3996x; 1.2277x over previous
#include <cuda_runtime.h>
#include <stdint.h>

#define HWC    (512*512)
#define NCH    64
#define NSEG   256
#define NB     4
#define CG     16            // channels per block
#define NCG    4
#define CHUNK  4096          // pixels per block = 8 image rows
#define NCHP   (HWC/CHUNK)   // 64 chunks per plane
#define TPB    256
#define NWARP  8
#define STRIP  512           // px per warp = one full image row
#define TPX    32            // px per warp-tile
#define NT     (STRIP/TPX)   // 16 tiles per warp
#define TROW   44            // tile row stride in u32 (16B-aligned rows, low conflict)

// Partial tables (encoded u32): [b][g][chunk][c(16)][s(256)]  16.8MB
__device__ unsigned g_scratch[(size_t)NB * NCG * NCHP * CG * NSEG];

// Monotone float->uint encoding; enc >= 1 for any non-NaN float, 0 = identity.
__device__ __forceinline__ unsigned enc_f32(float f) {
    unsigned b = __float_as_uint(f);
    return b ^ ((unsigned)((int)b >> 31) | 0x80000000u);
}

__global__ void __launch_bounds__(TPB, 5) seg_kernel(
    const float* __restrict__ feats,   // [B, C, 512, 512]
    const int*   __restrict__ labels)  // [B, 1, 512, 512]
{
    __shared__ unsigned smax[CG * 257];            // 16.4KB, stride 257
    __shared__ unsigned tiles[NWARP * CG * TROW];  // 22.0KB, per-warp [16][44]

    const int tid  = threadIdx.x;
    const int lane = tid & 31;
    const int w    = tid >> 5;
    unsigned* tile = tiles + w * (CG * TROW);

    const int chunk = blockIdx.x;
    const int g     = blockIdx.y;
    const int b     = blockIdx.z;
    const int row   = chunk * NWARP + w;           // this warp's image row
    const int sbase = row * 512;                   // strip base (plane-linear)
    const bool ybad = (row == 0) | (row == 511);

    for (int i = tid; i < CG * 257; i += TPB) smax[i] = 0u;
    __syncthreads();

    const int*   lb = labels + (size_t)b * HWC;
    const float* fb = feats + (size_t)(b * NCH + g * CG) * HWC;

    // Prefetch tile 0 (lane = pixel).
    float r[CG];
    int lab;
    {
        const int p = sbase + lane;
        #pragma unroll
        for (int c = 0; c < CG; ++c) r[c] = fb[(size_t)c * HWC + p];
        lab = lb[p];
    }

    const int cs = lane & 15;                 // process-phase channel
    const int h  = lane >> 4;                 // px half (0: px 0-15, 1: px 16-31)
    unsigned*    rowp = smax + cs * 257;
    const uint4* trow = (const uint4*)(tile + cs * TROW) + h * 4;

    for (int t = 0; t < NT; ++t) {
        // --- STS phase (lane = pixel): encode + border mask into warp tile ---
        {
            const bool bad = ybad | ((t == 0) & (lane == 0)) |
                                    ((t == NT - 1) & (lane == 31));
            #pragma unroll
            for (int c = 0; c < CG; ++c)
                tile[c * TROW + lane] = bad ? 0u : enc_f32(r[c]);
        }
        const int lab_cur = lab;
        __syncwarp();

        // --- Prefetch next tile (latency covered by process + other warps) ---
        if (t + 1 < NT) {
            const int p = sbase + (t + 1) * TPX + lane;
            #pragma unroll
            for (int c = 0; c < CG; ++c) r[c] = fb[(size_t)c * HWC + p];
            lab = lb[p];
        }

        // --- Process phase: lane = (half h, channel cs); near-CF smem ops ---
        #pragma unroll
        for (int q = 0; q < 4; ++q) {
            uint4 e4 = trow[q];
            const int pxb = h * 16 + 4 * q;
            int l0 = __shfl_sync(0xffffffffu, lab_cur, pxb + 0);
            int l1 = __shfl_sync(0xffffffffu, lab_cur, pxb + 1);
            int l2 = __shfl_sync(0xffffffffu, lab_cur, pxb + 2);
            int l3 = __shfl_sync(0xffffffffu, lab_cur, pxb + 3);
            atomicMax(rowp + l0, e4.x);
            atomicMax(rowp + l1, e4.y);
            atomicMax(rowp + l2, e4.z);
            atomicMax(rowp + l3, e4.w);
        }
        __syncwarp();
    }

    __syncthreads();
    // Dump private table to scratch (non-atomic, coalesced).
    unsigned* dst = g_scratch + (size_t)((b * NCG + g) * NCHP + chunk) * (CG * NSEG);
    for (int i = tid; i < CG * NSEG; i += TPB)
        dst[i] = smax[(i >> 8) * 257 + (i & 255)];
}

// Block per (b,g,c); thread = segment; 64 fully-coalesced k-rows of 1KB.
__global__ void __launch_bounds__(TPB) reduce_kernel(float* __restrict__ out) {
    const int x = blockIdx.x;                 // 0..255
    const int c = x & 15;
    const int g = (x >> 4) & 3;
    const int b = x >> 6;
    const int s = threadIdx.x;

    const unsigned* src = g_scratch
        + (size_t)((b * NCG + g) * NCHP) * (CG * NSEG) + c * NSEG + s;

    unsigned m0 = 0, m1 = 0, m2 = 0, m3 = 0;  // 4 chains for MLP
    #pragma unroll 4
    for (int k = 0; k < NCHP; k += 4) {
        m0 = max(m0, src[(size_t)(k + 0) * (CG * NSEG)]);
        m1 = max(m1, src[(size_t)(k + 1) * (CG * NSEG)]);
        m2 = max(m2, src[(size_t)(k + 2) * (CG * NSEG)]);
        m3 = max(m3, src[(size_t)(k + 3) * (CG * NSEG)]);
    }
    unsigned m = max(max(m0, m1), max(m2, m3));

    float rv;
    if (m == 0u) {
        rv = 0.0f;
    } else {
        unsigned bits = (m & 0x80000000u) ? (m ^ 0x80000000u) : ~m;
        rv = __uint_as_float(bits);
    }
    out[(size_t)(b * NCH + g * CG + c) * NSEG + s] = rv;
}

// Keeps ncu's fixed capture slot landing on seg_kernel.
__global__ void nop_kernel() {}

extern "C" void kernel_launch(void* const* d_in, const int* in_sizes, int n_in,
                              void* d_out, int out_size) {
    const float* feats  = (const float*)d_in[0];
    const int*   labels = (const int*)d_in[1];
    float*       out    = (float*)d_out;

    dim3 grid(NCHP, NCG, NB);                 // (64, 4, 4) = 1024 blocks
    seg_kernel<<<grid, TPB>>>(feats, labels);

    reduce_kernel<<<NB * NCG * CG, TPB>>>(out);

    nop_kernel<<<1, 32>>>();
}